// round 14
// baseline (speedup 1.0000x reference)
#include <cuda_runtime.h>
#include <cstdint>

#define BB 1024
#define TT 2048
#define DD 16
#define UU 4
#define HH 128
#define MM 4            // batch rows per CTA -> grid 256 -> 2 CTAs/SM
#define NT 256
#define PIT 24          // sIN/sH1/sH2 row pitch (floats)
#define PPIT 10         // sPart row pitch

typedef unsigned long long u64;

__device__ __forceinline__ uint32_t tf32r(float v) {
    uint32_t r; asm("cvt.rna.tf32.f32 %0, %1;" : "=r"(r) : "f"(v)); return r;
}
__device__ __forceinline__ float tanh_fast(float x) {
    float y; asm("tanh.approx.f32 %0, %1;" : "=f"(y) : "f"(x)); return y;
}
__device__ __forceinline__ void mma8(float* d, uint4 a, uint32_t b0, uint32_t b1) {
    asm volatile(
        "mma.sync.aligned.m16n8k8.row.col.f32.tf32.tf32.f32 "
        "{%0,%1,%2,%3}, {%4,%5,%6,%7}, {%8,%9}, {%0,%1,%2,%3};"
        : "+f"(d[0]), "+f"(d[1]), "+f"(d[2]), "+f"(d[3])
        : "r"(a.x), "r"(a.y), "r"(a.z), "r"(a.w), "r"(b0), "r"(b1));
}
__device__ __forceinline__ u64 pku(uint32_t lo, uint32_t hi) {
    return ((u64)hi << 32) | (u64)lo;
}

__global__ void __launch_bounds__(NT, 2)
gnsde_kernel(const float* __restrict__ carry,
             const float* __restrict__ x,
             const float* __restrict__ noise,
             const float* __restrict__ W0,
             const float* __restrict__ b0,
             const float* __restrict__ W1,
             const float* __restrict__ b1,
             const float* __restrict__ W2,
             const float* __restrict__ b2,
             float* __restrict__ out)
{
    __shared__ __align__(16) float sIN[DD * PIT];    // y rows (tf32 hi in cols 0-3 used)
    __shared__ __align__(16) float sX[MM * 4];       // x_t, fp32, [m][u]
    __shared__ __align__(16) float sH1[HH * PIT];
    __shared__ __align__(16) float sH2[HH * PIT];
    __shared__ __align__(16) float sPart[8 * 16 * PPIT];

    const int tid  = threadIdx.x;
    const int wid  = tid >> 5;
    const int lane = tid & 31;
    const int g    = lane >> 2;      // groupID
    const int tg   = lane & 3;       // threadID_in_group
    const int b0r  = blockIdx.x * MM;

    const int r0 = wid * 16 + g;     // A-fragment rows (j / d)
    const int r1 = r0 + 8;

    // ---- persistent weight fragments (1-term tf32: hi only) ----
    uint4 A1h[16];
#pragma unroll
    for (int c = 0; c < 16; ++c) {
        int k0 = 8 * c + tg, k1 = k0 + 4;
        A1h[c].x = tf32r(W1[k0 * HH + r0]);
        A1h[c].y = tf32r(W1[k0 * HH + r1]);
        A1h[c].z = tf32r(W1[k1 * HH + r0]);
        A1h[c].w = tf32r(W1[k1 * HH + r1]);
    }
    uint4 A0h[2];
#pragma unroll
    for (int c = 0; c < 2; ++c) {    // y rows only: k 0..15
        int k0 = 8 * c + tg, k1 = k0 + 4;
        A0h[c].x = tf32r(W0[k0 * HH + r0]);
        A0h[c].y = tf32r(W0[k0 * HH + r1]);
        A0h[c].z = tf32r(W0[k1 * HH + r0]);
        A0h[c].w = tf32r(W0[k1 * HH + r1]);
    }
    float w0xA[UU], w0xB[UU];        // W0 x-rows, fp32 exact
#pragma unroll
    for (int u = 0; u < UU; ++u) {
        w0xA[u] = W0[(DD + u) * HH + r0];
        w0xB[u] = W0[(DD + u) * HH + r1];
    }
    uint4 A2h[2];
#pragma unroll
    for (int i = 0; i < 2; ++i) {
        int c = 2 * wid + i;
        int k0 = 8 * c + tg, k1 = k0 + 4;
        A2h[i].x = tf32r(W2[k0 * DD + g]);
        A2h[i].y = tf32r(W2[k0 * DD + g + 8]);
        A2h[i].z = tf32r(W2[k1 * DD + g]);
        A2h[i].w = tf32r(W2[k1 * DD + g + 8]);
    }
    const float b0a = b0[r0], b0b = b0[r1];
    const float b1a = b1[r0], b1b = b1[r1];

    // gate identity (tid < 64): m = tid>>4 (0..3), d = tid&15
    const int mR = tid >> 4;
    const int dR = tid & 15;
    const float b2v = b2[dR];
    float yreg = 0.0f;

    uint32_t* sINu = (uint32_t*)sIN;
    uint32_t* sH1u = (uint32_t*)sH1;
    uint32_t* sH2u = (uint32_t*)sH2;
    // zero the m-columns so unused lanes read finite values
    for (int i = tid; i < DD * PIT; i += NT) sIN[i] = 0.0f;
    for (int i = tid; i < MM * 4; i += NT) sX[i] = 0.0f;
    __syncthreads();
    if (tid < 64) {
        yreg = carry[(size_t)(b0r + mR) * DD + dR];
        sINu[dR * PIT + mR] = tf32r(yreg);
    }
    if (tid >= 128 && tid < 128 + MM) {
        int m = tid & 3;
        float4 xv = *(const float4*)&x[((size_t)(b0r + m) * TT) * UU];
        *(float4*)&sX[m * 4] = xv;
    }

    const float alpha = 0.1f;
    const float onema = 0.9f;
    const float sqa   = 0.31622776601683794f;

    for (int t = 0; t < TT; ++t) {
        // ---- prefetch globals ----
        float nz = 0.0f;
        if (tid < 64) nz = noise[((size_t)(b0r + mR) * TT + t) * DD + dR];
        float4 xn = make_float4(0.f, 0.f, 0.f, 0.f);
        const bool xp = (tid >= 128 && tid < 128 + MM) && (t + 1 < TT);
        if (xp) xn = *(const float4*)&x[((size_t)(b0r + (tid & 3)) * TT + (t + 1)) * UU];

        __syncthreads();   // (1) y/x writes of prev step -> L0 reads

        // ===== layer 0: K=16 MMA over y + fp32 scalar x-fold =====
        {
            float P[4] = {0, 0, 0, 0};
#pragma unroll
            for (int c = 0; c < 2; ++c) {
                int rA = 8 * c + tg, rB = rA + 4;
                uint32_t bh0 = sINu[rA * PIT + g];
                uint32_t bh1 = sINu[rB * PIT + g];
                mma8(P, A0h[c], bh0, bh1);
            }
            // x-fold: m-cols 2tg, 2tg+1 (garbage beyond m=3 is contained per-column)
            float4 xa = *(const float4*)&sX[((2 * tg) & 3) * 4];
            float4 xb = *(const float4*)&sX[((2 * tg + 1) & 3) * 4];
            float s0 = w0xA[0] * xa.x + w0xA[1] * xa.y + w0xA[2] * xa.z + w0xA[3] * xa.w;
            float s1 = w0xA[0] * xb.x + w0xA[1] * xb.y + w0xA[2] * xb.z + w0xA[3] * xb.w;
            float s2 = w0xB[0] * xa.x + w0xB[1] * xa.y + w0xB[2] * xa.z + w0xB[3] * xa.w;
            float s3 = w0xB[0] * xb.x + w0xB[1] * xb.y + w0xB[2] * xb.z + w0xB[3] * xb.w;
            float h0 = tanh_fast(P[0] + s0 + b0a);
            float h1 = tanh_fast(P[1] + s1 + b0a);
            float h2 = tanh_fast(P[2] + s2 + b0b);
            float h3 = tanh_fast(P[3] + s3 + b0b);
            *(u64*)&sH1u[r0 * PIT + 2 * tg] = pku(tf32r(h0), tf32r(h1));
            *(u64*)&sH1u[r1 * PIT + 2 * tg] = pku(tf32r(h2), tf32r(h3));
        }
        __syncthreads();   // (2)

        // ===== layer 1: K=128, 16 chunks, 1-term TF32 =====
        {
            float P[4] = {0, 0, 0, 0};
#pragma unroll
            for (int c = 0; c < 16; ++c) {
                int rA = 8 * c + tg, rB = rA + 4;
                uint32_t bh0 = sH1u[rA * PIT + g];
                uint32_t bh1 = sH1u[rB * PIT + g];
                mma8(P, A1h[c], bh0, bh1);
            }
            float h0 = tanh_fast(P[0] + b1a);
            float h1 = tanh_fast(P[1] + b1a);
            float h2 = tanh_fast(P[2] + b1b);
            float h3 = tanh_fast(P[3] + b1b);
            *(u64*)&sH2u[r0 * PIT + 2 * tg] = pku(tf32r(h0), tf32r(h1));
            *(u64*)&sH2u[r1 * PIT + 2 * tg] = pku(tf32r(h2), tf32r(h3));
        }
        __syncthreads();   // (3)

        // ===== layer 2: k-split across warps (chunks 2w, 2w+1), 1-term =====
        {
            float P[4] = {0, 0, 0, 0};
#pragma unroll
            for (int i = 0; i < 2; ++i) {
                int rA = 8 * (2 * wid + i) + tg, rB = rA + 4;
                uint32_t bh0 = sH2u[rA * PIT + g];
                uint32_t bh1 = sH2u[rB * PIT + g];
                mma8(P, A2h[i], bh0, bh1);
            }
            *(float2*)&sPart[wid * 160 + g * PPIT + 2 * tg]       = make_float2(P[0], P[1]);
            *(float2*)&sPart[wid * 160 + (g + 8) * PPIT + 2 * tg] = make_float2(P[2], P[3]);
        }

        // (4) asymmetric: warps 0-1 sync (they reduce); warps 2-7 arrive and move on
        if (wid < 2) {
            asm volatile("bar.sync 1, %0;" :: "n"(NT) : "memory");
            // ===== reduce + gate + outputs: tid<64 = (mR, dR) =====
            float s = 0.0f;
#pragma unroll
            for (int w = 0; w < 8; ++w) s += sPart[w * 160 + dR * PPIT + mR];
            float mt = s + b2v;
            float mu = onema * yreg + alpha * mt;
            float yn = mu + sqa * nz;
            size_t base = ((size_t)(b0r + mR) * TT + t) * DD + dR;
            out[base]                        = yn;
            out[base + (size_t)BB * TT * DD] = mt;
            out[base + 2ull * BB * TT * DD]  = mu;
            yreg = yn;
            sINu[dR * PIT + mR] = tf32r(yn);
        } else {
            asm volatile("bar.arrive 1, %0;" :: "n"(NT) : "memory");
            if (xp) {
                int m = tid & 3;
                *(float4*)&sX[m * 4] = xn;   // x(t+1), fp32; ordered by bar (1)
            }
        }
    }
}

extern "C" void kernel_launch(void* const* d_in, const int* in_sizes, int n_in,
                              void* d_out, int out_size) {
    const float* carry = (const float*)d_in[0];
    const float* x     = (const float*)d_in[1];
    const float* noise = (const float*)d_in[2];
    const float* W0    = (const float*)d_in[3];
    const float* b0    = (const float*)d_in[4];
    const float* W1    = (const float*)d_in[5];
    const float* b1    = (const float*)d_in[6];
    const float* W2    = (const float*)d_in[7];
    const float* b2    = (const float*)d_in[8];
    float* out = (float*)d_out;

    gnsde_kernel<<<BB / MM, NT>>>(carry, x, noise, W0, b0, W1, b1, W2, b2, out);
}

// round 15
// speedup vs baseline: 1.4218x; 1.4218x over previous
#include <cuda_runtime.h>
#include <cstdint>

#define BB 1024
#define TT 2048
#define DD 16
#define UU 4
#define HH 128
#define MM 8
#define NT 256
#define PIT 24          // sIN/sH1/sH2 row pitch (floats)
#define PPIT 10         // sPart row pitch

typedef unsigned long long u64;

__device__ __forceinline__ uint32_t tf32r(float v) {
    uint32_t r; asm("cvt.rna.tf32.f32 %0, %1;" : "=r"(r) : "f"(v)); return r;
}
__device__ __forceinline__ float tanh_fast(float x) {
    float y; asm("tanh.approx.f32 %0, %1;" : "=f"(y) : "f"(x)); return y;
}
__device__ __forceinline__ void mma8(float* d, uint4 a, uint32_t b0, uint32_t b1) {
    asm volatile(
        "mma.sync.aligned.m16n8k8.row.col.f32.tf32.tf32.f32 "
        "{%0,%1,%2,%3}, {%4,%5,%6,%7}, {%8,%9}, {%0,%1,%2,%3};"
        : "+f"(d[0]), "+f"(d[1]), "+f"(d[2]), "+f"(d[3])
        : "r"(a.x), "r"(a.y), "r"(a.z), "r"(a.w), "r"(b0), "r"(b1));
}
__device__ __forceinline__ u64 pku(uint32_t lo, uint32_t hi) {
    return ((u64)hi << 32) | (u64)lo;
}

__global__ void __launch_bounds__(NT, 1)
gnsde_kernel(const float* __restrict__ carry,
             const float* __restrict__ x,
             const float* __restrict__ noise,
             const float* __restrict__ W0,
             const float* __restrict__ b0,
             const float* __restrict__ W1,
             const float* __restrict__ b1,
             const float* __restrict__ W2,
             const float* __restrict__ b2,
             float* __restrict__ out)
{
    __shared__ __align__(16) float sIN[DD * PIT];    // y rows (tf32 hi in cols 0-7)
    __shared__ __align__(16) float sX[MM * 4];       // x_t, fp32, [m][u]
    __shared__ __align__(16) float sH1[HH * PIT];
    __shared__ __align__(16) float sH2[HH * PIT];
    __shared__ __align__(16) float sPart[8 * 16 * PPIT];

    const int tid  = threadIdx.x;
    const int wid  = tid >> 5;
    const int lane = tid & 31;
    const int g    = lane >> 2;      // groupID
    const int tg   = lane & 3;       // threadID_in_group
    const int b0r  = blockIdx.x * MM;

    const int r0 = wid * 16 + g;     // A-fragment rows (j / d)
    const int r1 = r0 + 8;

    // ---- persistent weight fragments (1-term tf32) ----
    uint4 A1h[16];
#pragma unroll
    for (int c = 0; c < 16; ++c) {
        int k0 = 8 * c + tg, k1 = k0 + 4;
        A1h[c].x = tf32r(W1[k0 * HH + r0]);
        A1h[c].y = tf32r(W1[k0 * HH + r1]);
        A1h[c].z = tf32r(W1[k1 * HH + r0]);
        A1h[c].w = tf32r(W1[k1 * HH + r1]);
    }
    uint4 A0h[2];
#pragma unroll
    for (int c = 0; c < 2; ++c) {    // y rows only: k 0..15
        int k0 = 8 * c + tg, k1 = k0 + 4;
        A0h[c].x = tf32r(W0[k0 * HH + r0]);
        A0h[c].y = tf32r(W0[k0 * HH + r1]);
        A0h[c].z = tf32r(W0[k1 * HH + r0]);
        A0h[c].w = tf32r(W0[k1 * HH + r1]);
    }
    float w0xA[UU], w0xB[UU];        // W0 x-rows, fp32 exact
#pragma unroll
    for (int u = 0; u < UU; ++u) {
        w0xA[u] = W0[(DD + u) * HH + r0];
        w0xB[u] = W0[(DD + u) * HH + r1];
    }
    uint4 A2h[2];
#pragma unroll
    for (int i = 0; i < 2; ++i) {
        int c = 2 * wid + i;
        int k0 = 8 * c + tg, k1 = k0 + 4;
        A2h[i].x = tf32r(W2[k0 * DD + g]);
        A2h[i].y = tf32r(W2[k0 * DD + g + 8]);
        A2h[i].z = tf32r(W2[k1 * DD + g]);
        A2h[i].w = tf32r(W2[k1 * DD + g + 8]);
    }
    const float b0a = b0[r0], b0b = b0[r1];
    const float b1a = b1[r0], b1b = b1[r1];

    // gate identity (tid < 128): m = tid>>4, d = tid&15
    const int mR = tid >> 4;
    const int dR = tid & 15;
    const float b2v = b2[dR];
    float yreg = 0.0f;

    uint32_t* sINu = (uint32_t*)sIN;
    uint32_t* sH1u = (uint32_t*)sH1;
    uint32_t* sH2u = (uint32_t*)sH2;
    if (tid < 128) {
        yreg = carry[(size_t)(b0r + mR) * DD + dR];
        sINu[dR * PIT + mR] = tf32r(yreg);
    }
    if (tid >= 128 && tid < 128 + MM) {
        int m = tid & 7;
        float4 xv = *(const float4*)&x[((size_t)(b0r + m) * TT) * UU];
        *(float4*)&sX[m * 4] = xv;
    }

    const float alpha = 0.1f;
    const float onema = 0.9f;
    const float sqa   = 0.31622776601683794f;

    for (int t = 0; t < TT; ++t) {
        // ---- prefetch globals ----
        float nz = 0.0f;
        if (tid < 128) nz = noise[((size_t)(b0r + mR) * TT + t) * DD + dR];
        float4 xn = make_float4(0.f, 0.f, 0.f, 0.f);
        const bool xp = (tid >= 128 && tid < 128 + MM) && (t + 1 < TT);
        if (xp) xn = *(const float4*)&x[((size_t)(b0r + (tid & 7)) * TT + (t + 1)) * UU];

        __syncthreads();   // (1) y/x writes of prev step -> L0 reads

        // ===== layer 0: K=16 MMA over y + fp32 scalar x-fold =====
        {
            float P[4] = {0, 0, 0, 0};
#pragma unroll
            for (int c = 0; c < 2; ++c) {
                int rA = 8 * c + tg, rB = rA + 4;
                uint32_t bh0 = sINu[rA * PIT + g];
                uint32_t bh1 = sINu[rB * PIT + g];
                mma8(P, A0h[c], bh0, bh1);
            }
            float4 xa = *(const float4*)&sX[(2 * tg) * 4];
            float4 xb = *(const float4*)&sX[(2 * tg + 1) * 4];
            float s0 = w0xA[0] * xa.x + w0xA[1] * xa.y + w0xA[2] * xa.z + w0xA[3] * xa.w;
            float s1 = w0xA[0] * xb.x + w0xA[1] * xb.y + w0xA[2] * xb.z + w0xA[3] * xb.w;
            float s2 = w0xB[0] * xa.x + w0xB[1] * xa.y + w0xB[2] * xa.z + w0xB[3] * xa.w;
            float s3 = w0xB[0] * xb.x + w0xB[1] * xb.y + w0xB[2] * xb.z + w0xB[3] * xb.w;
            float h0 = tanh_fast(P[0] + s0 + b0a);
            float h1 = tanh_fast(P[1] + s1 + b0a);
            float h2 = tanh_fast(P[2] + s2 + b0b);
            float h3 = tanh_fast(P[3] + s3 + b0b);
            *(u64*)&sH1u[r0 * PIT + 2 * tg] = pku(tf32r(h0), tf32r(h1));
            *(u64*)&sH1u[r1 * PIT + 2 * tg] = pku(tf32r(h2), tf32r(h3));
        }
        __syncthreads();   // (2)

        // ===== layer 1: K=128, 16 chunks, 1-term TF32 =====
        {
            float P[4] = {0, 0, 0, 0};
#pragma unroll
            for (int c = 0; c < 16; ++c) {
                int rA = 8 * c + tg, rB = rA + 4;
                uint32_t bh0 = sH1u[rA * PIT + g];
                uint32_t bh1 = sH1u[rB * PIT + g];
                mma8(P, A1h[c], bh0, bh1);
            }
            float h0 = tanh_fast(P[0] + b1a);
            float h1 = tanh_fast(P[1] + b1a);
            float h2 = tanh_fast(P[2] + b1b);
            float h3 = tanh_fast(P[3] + b1b);
            *(u64*)&sH2u[r0 * PIT + 2 * tg] = pku(tf32r(h0), tf32r(h1));
            *(u64*)&sH2u[r1 * PIT + 2 * tg] = pku(tf32r(h2), tf32r(h3));
        }
        __syncthreads();   // (3)

        // ===== layer 2: k-split across warps (chunks 2w, 2w+1), 1-term =====
        {
            float P[4] = {0, 0, 0, 0};
#pragma unroll
            for (int i = 0; i < 2; ++i) {
                int rA = 8 * (2 * wid + i) + tg, rB = rA + 4;
                uint32_t bh0 = sH2u[rA * PIT + g];
                uint32_t bh1 = sH2u[rB * PIT + g];
                mma8(P, A2h[i], bh0, bh1);
            }
            *(float2*)&sPart[wid * 160 + g * PPIT + 2 * tg]       = make_float2(P[0], P[1]);
            *(float2*)&sPart[wid * 160 + (g + 8) * PPIT + 2 * tg] = make_float2(P[2], P[3]);
        }

        // (4) asymmetric: warps 0-3 sync (they reduce); warps 4-7 arrive and move on
        if (wid < 4) {
            asm volatile("bar.sync 1, %0;" :: "n"(NT) : "memory");
            // ===== reduce + gate + outputs: tid<128 = (mR, dR) =====
            float s = 0.0f;
#pragma unroll
            for (int w = 0; w < 8; ++w) s += sPart[w * 160 + dR * PPIT + mR];
            float mt = s + b2v;
            float mu = onema * yreg + alpha * mt;
            float yn = mu + sqa * nz;
            size_t base = ((size_t)(b0r + mR) * TT + t) * DD + dR;
            out[base]                        = yn;
            out[base + (size_t)BB * TT * DD] = mt;
            out[base + 2ull * BB * TT * DD]  = mu;
            yreg = yn;
            sINu[dR * PIT + mR] = tf32r(yn);
        } else {
            asm volatile("bar.arrive 1, %0;" :: "n"(NT) : "memory");
            if (xp) {
                int m = tid & 7;
                *(float4*)&sX[m * 4] = xn;   // x(t+1), fp32; ordered by bar (1)
            }
        }
    }
}

extern "C" void kernel_launch(void* const* d_in, const int* in_sizes, int n_in,
                              void* d_out, int out_size) {
    const float* carry = (const float*)d_in[0];
    const float* x     = (const float*)d_in[1];
    const float* noise = (const float*)d_in[2];
    const float* W0    = (const float*)d_in[3];
    const float* b0    = (const float*)d_in[4];
    const float* W1    = (const float*)d_in[5];
    const float* b1    = (const float*)d_in[6];
    const float* W2    = (const float*)d_in[7];
    const float* b2    = (const float*)d_in[8];
    float* out = (float*)d_out;

    gnsde_kernel<<<BB / MM, NT>>>(carry, x, noise, W0, b0, W1, b1, W2, b2, out);
}

// round 16
// speedup vs baseline: 1.5157x; 1.0660x over previous
#include <cuda_runtime.h>
#include <cstdint>

#define BB 1024
#define TT 2048
#define DD 16
#define UU 4
#define HH 128
#define MM 8
#define NT 256
#define PIT 24          // sIN/sH1/sH2 row pitch (floats)
#define PPIT 10         // sPart row pitch

typedef unsigned long long u64;

__device__ __forceinline__ uint32_t tf32r(float v) {
    uint32_t r; asm("cvt.rna.tf32.f32 %0, %1;" : "=r"(r) : "f"(v)); return r;
}
__device__ __forceinline__ float tanh_fast(float x) {
    float y; asm("tanh.approx.f32 %0, %1;" : "=f"(y) : "f"(x)); return y;
}
__device__ __forceinline__ void mma8(float* d, uint4 a, uint32_t b0, uint32_t b1) {
    asm volatile(
        "mma.sync.aligned.m16n8k8.row.col.f32.tf32.tf32.f32 "
        "{%0,%1,%2,%3}, {%4,%5,%6,%7}, {%8,%9}, {%0,%1,%2,%3};"
        : "+f"(d[0]), "+f"(d[1]), "+f"(d[2]), "+f"(d[3])
        : "r"(a.x), "r"(a.y), "r"(a.z), "r"(a.w), "r"(b0), "r"(b1));
}
__device__ __forceinline__ u64 pku(uint32_t lo, uint32_t hi) {
    return ((u64)hi << 32) | (u64)lo;
}

__global__ void __launch_bounds__(NT, 1)
gnsde_kernel(const float* __restrict__ carry,
             const float* __restrict__ x,
             const float* __restrict__ noise,
             const float* __restrict__ W0,
             const float* __restrict__ b0,
             const float* __restrict__ W1,
             const float* __restrict__ b1,
             const float* __restrict__ W2,
             const float* __restrict__ b2,
             float* __restrict__ out)
{
    __shared__ __align__(16) float sIN[DD * PIT];    // y rows (tf32 hi in cols 0-7)
    __shared__ __align__(16) float sX[MM * 4];       // x_t, fp32, [m][u]
    __shared__ __align__(16) float sH1[HH * PIT];
    __shared__ __align__(16) float sH2[HH * PIT];
    __shared__ __align__(16) float sPart[8 * 16 * PPIT];

    const int tid  = threadIdx.x;
    const int wid  = tid >> 5;
    const int lane = tid & 31;
    const int g    = lane >> 2;      // groupID
    const int tg   = lane & 3;       // threadID_in_group
    const int b0r  = blockIdx.x * MM;

    const int r0 = wid * 16 + g;     // A-fragment rows (j / d)
    const int r1 = r0 + 8;

    // ---- persistent weight fragments (1-term tf32) ----
    uint4 A1h[16];
#pragma unroll
    for (int c = 0; c < 16; ++c) {
        int k0 = 8 * c + tg, k1 = k0 + 4;
        A1h[c].x = tf32r(W1[k0 * HH + r0]);
        A1h[c].y = tf32r(W1[k0 * HH + r1]);
        A1h[c].z = tf32r(W1[k1 * HH + r0]);
        A1h[c].w = tf32r(W1[k1 * HH + r1]);
    }
    uint4 A0h[2];
#pragma unroll
    for (int c = 0; c < 2; ++c) {    // y rows only: k 0..15
        int k0 = 8 * c + tg, k1 = k0 + 4;
        A0h[c].x = tf32r(W0[k0 * HH + r0]);
        A0h[c].y = tf32r(W0[k0 * HH + r1]);
        A0h[c].z = tf32r(W0[k1 * HH + r0]);
        A0h[c].w = tf32r(W0[k1 * HH + r1]);
    }
    float w0xA[UU], w0xB[UU];        // W0 x-rows, fp32 exact
#pragma unroll
    for (int u = 0; u < UU; ++u) {
        w0xA[u] = W0[(DD + u) * HH + r0];
        w0xB[u] = W0[(DD + u) * HH + r1];
    }
    uint4 A2h[2];
#pragma unroll
    for (int i = 0; i < 2; ++i) {
        int c = 2 * wid + i;
        int k0 = 8 * c + tg, k1 = k0 + 4;
        A2h[i].x = tf32r(W2[k0 * DD + g]);
        A2h[i].y = tf32r(W2[k0 * DD + g + 8]);
        A2h[i].z = tf32r(W2[k1 * DD + g]);
        A2h[i].w = tf32r(W2[k1 * DD + g + 8]);
    }
    const float b0a = b0[r0], b0b = b0[r1];
    const float b1a = b1[r0], b1b = b1[r1];

    // gate identity (tid < 128): m = tid>>4, d = tid&15
    const int mR = tid >> 4;
    const int dR = tid & 15;
    const float b2v = b2[dR];
    float yreg = 0.0f;

    uint32_t* sINu = (uint32_t*)sIN;
    uint32_t* sH1u = (uint32_t*)sH1;
    uint32_t* sH2u = (uint32_t*)sH2;
    if (tid < 128) {
        yreg = carry[(size_t)(b0r + mR) * DD + dR];
        sINu[dR * PIT + mR] = tf32r(yreg);
    }
    if (tid >= 128 && tid < 128 + MM) {
        int m = tid & 7;
        float4 xv = *(const float4*)&x[((size_t)(b0r + m) * TT) * UU];
        *(float4*)&sX[m * 4] = xv;
    }

    const float alpha = 0.1f;
    const float onema = 0.9f;
    const float sqa   = 0.31622776601683794f;

    for (int t = 0; t < TT; ++t) {
        // ---- prefetch globals ----
        float nz = 0.0f;
        if (tid < 128) nz = noise[((size_t)(b0r + mR) * TT + t) * DD + dR];
        float4 xn = make_float4(0.f, 0.f, 0.f, 0.f);
        const bool xp = (tid >= 128 && tid < 128 + MM) && (t + 1 < TT);
        if (xp) xn = *(const float4*)&x[((size_t)(b0r + (tid & 7)) * TT + (t + 1)) * UU];

        __syncthreads();   // (1) y/x writes of prev step -> L0 reads

        // ===== layer 0: K=16 MMA (2 independent chains) + fp32 x-fold =====
        {
            float P0[4] = {0, 0, 0, 0}, P1[4] = {0, 0, 0, 0};
            {
                uint32_t a0 = sINu[tg * PIT + g];
                uint32_t a1 = sINu[(tg + 4) * PIT + g];
                uint32_t c0 = sINu[(8 + tg) * PIT + g];
                uint32_t c1 = sINu[(12 + tg) * PIT + g];
                mma8(P0, A0h[0], a0, a1);
                mma8(P1, A0h[1], c0, c1);
            }
            float4 xa = *(const float4*)&sX[(2 * tg) * 4];
            float4 xb = *(const float4*)&sX[(2 * tg + 1) * 4];
            float s0 = w0xA[0] * xa.x + w0xA[1] * xa.y + w0xA[2] * xa.z + w0xA[3] * xa.w;
            float s1 = w0xA[0] * xb.x + w0xA[1] * xb.y + w0xA[2] * xb.z + w0xA[3] * xb.w;
            float s2 = w0xB[0] * xa.x + w0xB[1] * xa.y + w0xB[2] * xa.z + w0xB[3] * xa.w;
            float s3 = w0xB[0] * xb.x + w0xB[1] * xb.y + w0xB[2] * xb.z + w0xB[3] * xb.w;
            float h0 = tanh_fast((P0[0] + P1[0]) + s0 + b0a);
            float h1 = tanh_fast((P0[1] + P1[1]) + s1 + b0a);
            float h2 = tanh_fast((P0[2] + P1[2]) + s2 + b0b);
            float h3 = tanh_fast((P0[3] + P1[3]) + s3 + b0b);
            *(u64*)&sH1u[r0 * PIT + 2 * tg] = pku(tf32r(h0), tf32r(h1));
            *(u64*)&sH1u[r1 * PIT + 2 * tg] = pku(tf32r(h2), tf32r(h3));
        }
        __syncthreads();   // (2)

        // ===== layer 1: K=128, 16 chunks in 4 independent chains =====
        {
            float P0[4] = {0, 0, 0, 0}, P1[4] = {0, 0, 0, 0};
            float P2[4] = {0, 0, 0, 0}, P3[4] = {0, 0, 0, 0};
#pragma unroll
            for (int q = 0; q < 4; ++q) {        // 4 rounds x 4 chains
                int cb = 4 * q;
                int rA0 = 8 * (cb + 0) + tg;
                int rA1 = 8 * (cb + 1) + tg;
                int rA2 = 8 * (cb + 2) + tg;
                int rA3 = 8 * (cb + 3) + tg;
                uint32_t b00 = sH1u[rA0 * PIT + g], b01 = sH1u[(rA0 + 4) * PIT + g];
                uint32_t b10 = sH1u[rA1 * PIT + g], b11 = sH1u[(rA1 + 4) * PIT + g];
                uint32_t b20 = sH1u[rA2 * PIT + g], b21 = sH1u[(rA2 + 4) * PIT + g];
                uint32_t b30 = sH1u[rA3 * PIT + g], b31 = sH1u[(rA3 + 4) * PIT + g];
                mma8(P0, A1h[cb + 0], b00, b01);
                mma8(P1, A1h[cb + 1], b10, b11);
                mma8(P2, A1h[cb + 2], b20, b21);
                mma8(P3, A1h[cb + 3], b30, b31);
            }
            float h0 = tanh_fast(((P0[0] + P1[0]) + (P2[0] + P3[0])) + b1a);
            float h1 = tanh_fast(((P0[1] + P1[1]) + (P2[1] + P3[1])) + b1a);
            float h2 = tanh_fast(((P0[2] + P1[2]) + (P2[2] + P3[2])) + b1b);
            float h3 = tanh_fast(((P0[3] + P1[3]) + (P2[3] + P3[3])) + b1b);
            *(u64*)&sH2u[r0 * PIT + 2 * tg] = pku(tf32r(h0), tf32r(h1));
            *(u64*)&sH2u[r1 * PIT + 2 * tg] = pku(tf32r(h2), tf32r(h3));
        }
        __syncthreads();   // (3)

        // ===== layer 2: k-split across warps, 2 independent chains =====
        {
            float P0[4] = {0, 0, 0, 0}, P1[4] = {0, 0, 0, 0};
            {
                int rA = 8 * (2 * wid) + tg;
                int rB = 8 * (2 * wid + 1) + tg;
                uint32_t a0 = sH2u[rA * PIT + g], a1 = sH2u[(rA + 4) * PIT + g];
                uint32_t c0 = sH2u[rB * PIT + g], c1 = sH2u[(rB + 4) * PIT + g];
                mma8(P0, A2h[0], a0, a1);
                mma8(P1, A2h[1], c0, c1);
            }
            *(float2*)&sPart[wid * 160 + g * PPIT + 2 * tg] =
                make_float2(P0[0] + P1[0], P0[1] + P1[1]);
            *(float2*)&sPart[wid * 160 + (g + 8) * PPIT + 2 * tg] =
                make_float2(P0[2] + P1[2], P0[3] + P1[3]);
        }

        // (4) asymmetric: warps 0-3 sync (they reduce); warps 4-7 arrive and move on
        if (wid < 4) {
            asm volatile("bar.sync 1, %0;" :: "n"(NT) : "memory");
            // ===== reduce + gate + outputs: tid<128 = (mR, dR) =====
            float s = 0.0f;
#pragma unroll
            for (int w = 0; w < 8; ++w) s += sPart[w * 160 + dR * PPIT + mR];
            float mt = s + b2v;
            float mu = onema * yreg + alpha * mt;
            float yn = mu + sqa * nz;
            yreg = yn;
            sINu[dR * PIT + mR] = tf32r(yn);   // publish state first (critical path)
            size_t base = ((size_t)(b0r + mR) * TT + t) * DD + dR;
            out[base]                        = yn;
            out[base + (size_t)BB * TT * DD] = mt;
            out[base + 2ull * BB * TT * DD]  = mu;
        } else {
            asm volatile("bar.arrive 1, %0;" :: "n"(NT) : "memory");
            if (xp) {
                int m = tid & 7;
                *(float4*)&sX[m * 4] = xn;   // x(t+1), fp32; ordered by bar (1)
            }
        }
    }
}

extern "C" void kernel_launch(void* const* d_in, const int* in_sizes, int n_in,
                              void* d_out, int out_size) {
    const float* carry = (const float*)d_in[0];
    const float* x     = (const float*)d_in[1];
    const float* noise = (const float*)d_in[2];
    const float* W0    = (const float*)d_in[3];
    const float* b0    = (const float*)d_in[4];
    const float* W1    = (const float*)d_in[5];
    const float* b1    = (const float*)d_in[6];
    const float* W2    = (const float*)d_in[7];
    const float* b2    = (const float*)d_in[8];
    float* out = (float*)d_out;

    gnsde_kernel<<<BB / MM, NT>>>(carry, x, noise, W0, b0, W1, b1, W2, b2, out);
}